// round 15
// baseline (speedup 1.0000x reference)
#include <cuda_runtime.h>
#include <cuda_bf16.h>
#include <cuda_fp16.h>
#include <math.h>
#include <stdint.h>

#define NN 20000
#define EE 320000
#define EH 160000
#define EPSV 1e-6f

// ---------------- scratch (static device globals; no allocs) ----------------
__device__ float g_h1[NN * 64];
__device__ float g_h[NN * 128];
__device__ __half g_Ph[NN * 128];      // [A|B] per node, fp16
__device__ float g_Wab[128 * 128];
__device__ float g_Wc[256 * 64];       // [w_in2 ; Wab@w_in2]
__device__ float g_bP[128];            // Wab @ b_in2
__device__ float g_Weff0[128 * 128];
__device__ float g_Weff1[128 * 128];
__device__ float g_maps[EE * 4];
__device__ float4 g_diag4[NN];         // FtF per node (written by k3b, no atomics)
__device__ float g_diagn[NN * 4];
__device__ float g_offn[EE * 4];       // CSR order
__device__ __half g_Hth[NN * 128];     // Ht fp16
__device__ int g_deg[NN];
__device__ int g_cursor[NN];
__device__ int g_rowptr[NN + 1];
__device__ int2 g_adjdst[EE];          // CSR slot -> (edge id, dst)
__device__ int g_pos[EE];              // edge id -> CSR slot

__device__ __forceinline__ float eluf(float v) {
    return v > 0.f ? v : (expf(v) - 1.f);
}

__device__ __forceinline__ float4 dinv_closed(float f00, float f01, float f11) {
    float t = 0.5f * (f00 + f11);
    float dd = 0.5f * (f00 - f11);
    float rad = sqrtf(dd * dd + f01 * f01);
    float s1 = rsqrtf(fmaxf(t - rad, EPSV));
    float s2 = rsqrtf(fmaxf(t + rad, EPSV));
    float c0 = 0.5f * (s1 + s2);
    float c1 = (rad > 1e-20f) ? (s2 - s1) / (2.f * rad) : 0.f;
    return make_float4(c0 + c1 * dd, c1 * f01, c1 * f01, c0 - c1 * dd);
}

__device__ __forceinline__ uint32_t packbf(__nv_bfloat16 a, __nv_bfloat16 b) {
    __nv_bfloat162 t = __halves2bfloat162(a, b);
    return *reinterpret_cast<uint32_t*>(&t);
}

#define MMA16816(c, a, b0_, b1_)                                             \
    asm volatile(                                                            \
        "mma.sync.aligned.m16n8k16.row.col.f32.bf16.bf16.f32 "               \
        "{%0,%1,%2,%3}, {%4,%5,%6,%7}, {%8,%9}, {%0,%1,%2,%3};"              \
        : "+f"((c)[0]), "+f"((c)[1]), "+f"((c)[2]), "+f"((c)[3])             \
        : "r"((a)[0]), "r"((a)[1]), "r"((a)[2]), "r"((a)[3]),                \
          "r"(b0_), "r"(b1_))

// ---------------- tensor-core GEMM body; HOUT -> __half output ----------------
template <int BN, bool RELU, bool HOUT>
__device__ __forceinline__ void gemm_body(const float* __restrict__ A,
                                          const float* __restrict__ W,
                                          const float* __restrict__ bias,
                                          void* __restrict__ Cout,
                                          int M, int N, int K, int bm, int bn, int ldc) {
    constexpr int BM = 64;
    constexpr int WN = BN / 4;
    constexpr int NSUB = WN / 8;
    constexpr int SW = 12;

    __shared__ uint32_t sAh[BM * SW], sAl[BM * SW];
    __shared__ uint32_t sWh[BN * SW], sWl[BN * SW];

    const int tid = threadIdx.x;
    const int lane = tid & 31;
    const int wid = tid >> 5;
    const int warp_m = wid & 1;
    const int warp_n = wid >> 1;
    const int qr = lane >> 2;
    const int qc = lane & 3;

    const int lm = tid >> 2;
    const int lk = (tid & 3) * 4;
    const int wof = lk >> 1;

    float acc[2][NSUB][4];
#pragma unroll
    for (int i = 0; i < 2; i++)
#pragma unroll
        for (int j = 0; j < NSUB; j++)
#pragma unroll
            for (int q = 0; q < 4; q++) acc[i][j][q] = 0.f;

    float4 a_reg;
    float4 w_reg[BN / 64];

    auto loadA = [&](int k0) {
        int m = bm + lm;
        a_reg = (m < M) ? *(const float4*)(A + (size_t)m * K + k0 + lk)
                        : make_float4(0.f, 0.f, 0.f, 0.f);
    };
    auto loadW = [&](int k0) {
#pragma unroll
        for (int i = 0; i < BN / 64; i++) {
            int n = bn + lm + i * 64;
            w_reg[i] = (n < N) ? *(const float4*)(W + (size_t)n * K + k0 + lk)
                               : make_float4(0.f, 0.f, 0.f, 0.f);
        }
    };

    auto storeSplit = [&](uint32_t* hi, uint32_t* lo, int row, float4 v) {
        __nv_bfloat16 h0 = __float2bfloat16(v.x), h1 = __float2bfloat16(v.y);
        __nv_bfloat16 h2 = __float2bfloat16(v.z), h3 = __float2bfloat16(v.w);
        __nv_bfloat16 l0 = __float2bfloat16(v.x - __bfloat162float(h0));
        __nv_bfloat16 l1 = __float2bfloat16(v.y - __bfloat162float(h1));
        __nv_bfloat16 l2 = __float2bfloat16(v.z - __bfloat162float(h2));
        __nv_bfloat16 l3 = __float2bfloat16(v.w - __bfloat162float(h3));
        int w0 = row * SW + wof;
        hi[w0 + 0] = packbf(h0, h1);
        hi[w0 + 1] = packbf(h2, h3);
        lo[w0 + 0] = packbf(l0, l1);
        lo[w0 + 1] = packbf(l2, l3);
    };

    loadA(0);
    loadW(0);

    for (int k0 = 0; k0 < K; k0 += 16) {
        storeSplit(sAh, sAl, lm, a_reg);
#pragma unroll
        for (int i = 0; i < BN / 64; i++) storeSplit(sWh, sWl, lm + i * 64, w_reg[i]);
        __syncthreads();

        if (k0 + 16 < K) {
            loadA(k0 + 16);
            loadW(k0 + 16);
        }

        uint32_t ah[2][4], al[2][4];
#pragma unroll
        for (int ms = 0; ms < 2; ms++) {
            int r = warp_m * 32 + ms * 16 + qr;
            int b0 = r * SW + qc;
            ah[ms][0] = sAh[b0];
            ah[ms][1] = sAh[b0 + 8 * SW];
            ah[ms][2] = sAh[b0 + 4];
            ah[ms][3] = sAh[b0 + 8 * SW + 4];
            al[ms][0] = sAl[b0];
            al[ms][1] = sAl[b0 + 8 * SW];
            al[ms][2] = sAl[b0 + 4];
            al[ms][3] = sAl[b0 + 8 * SW + 4];
        }

#pragma unroll
        for (int ns = 0; ns < NSUB; ns++) {
            int n = warp_n * WN + ns * 8 + qr;
            int b = n * SW + qc;
            uint32_t bh0 = sWh[b], bh1 = sWh[b + 4];
            uint32_t bl0 = sWl[b], bl1 = sWl[b + 4];
#pragma unroll
            for (int ms = 0; ms < 2; ms++) {
                MMA16816(acc[ms][ns], ah[ms], bh0, bh1);
                MMA16816(acc[ms][ns], ah[ms], bl0, bl1);
                MMA16816(acc[ms][ns], al[ms], bh0, bh1);
            }
        }
        __syncthreads();
    }

#pragma unroll
    for (int ms = 0; ms < 2; ms++) {
#pragma unroll
        for (int ns = 0; ns < NSUB; ns++) {
            int m0 = bm + warp_m * 32 + ms * 16 + qr;
            int n0 = bn + warp_n * WN + ns * 8 + 2 * qc;
            const float* c = acc[ms][ns];
#pragma unroll
            for (int half = 0; half < 2; half++) {
                int m = m0 + half * 8;
                if (m >= M) continue;
                float v0 = c[half * 2 + 0];
                float v1 = c[half * 2 + 1];
                if (n0 + 1 < N) {
                    v0 += bias ? bias[n0] : 0.f;
                    v1 += bias ? bias[n0 + 1] : 0.f;
                    if (RELU) { v0 = fmaxf(v0, 0.f); v1 = fmaxf(v1, 0.f); }
                    if (HOUT) {
                        *(__half2*)((__half*)Cout + (size_t)m * ldc + n0) =
                            __floats2half2_rn(v0, v1);
                    } else {
                        *(float2*)((float*)Cout + (size_t)m * ldc + n0) =
                            make_float2(v0, v1);
                    }
                } else if (n0 < N) {
                    v0 += bias ? bias[n0] : 0.f;
                    if (RELU) v0 = fmaxf(v0, 0.f);
                    if (HOUT) {
                        ((__half*)Cout)[(size_t)m * ldc + n0] = __float2half_rn(v0);
                    } else {
                        ((float*)Cout)[(size_t)m * ldc + n0] = v0;
                    }
                }
            }
        }
    }
}

// ---------------- prep ----------------
__global__ void prep_k(const float* __restrict__ w_map1,
                       const float* __restrict__ W1_0, const float* __restrict__ W2_0,
                       const float* __restrict__ W1_1, const float* __restrict__ W2_1) {
    int i = blockIdx.x * blockDim.x + threadIdx.x;
    if (i < 128 * 128) {
        int j = i >> 7, k = i & 127;
        g_Wab[i] = (j < 64) ? w_map1[j * 256 + k] : w_map1[(j - 64) * 256 + 128 + k];
        int r = i >> 7, c = i & 127;
        int ii = r >> 6, g = r & 63;
        int jj = c >> 6, f = c & 63;
        g_Weff0[i] = W1_0[jj * 2 + ii] * W2_0[g * 64 + f];
        g_Weff1[i] = W1_1[jj * 2 + ii] * W2_1[g * 64 + f];
    }
    if (i < NN) {
        g_deg[i] = 0;
        g_cursor[i] = 0;
    }
}

// ---------------- K1: input-MLP gemm || hist || weight combine ----------------
__global__ void __launch_bounds__(256) k1_k(const float* __restrict__ x,
                                            const float* __restrict__ w_in1,
                                            const float* __restrict__ b_in1,
                                            const int* __restrict__ src,
                                            const float* __restrict__ w_in2,
                                            const float* __restrict__ b_in2) {
    int b = blockIdx.x;
    if (b < 313) {
        gemm_body<64, true, false>(x, w_in1, b_in1, g_h1, NN, 64, 512, b * 64, 0, 64);
    } else if (b < 1563) {
        int e = (b - 313) * 256 + threadIdx.x;
        if (e < EE) atomicAdd(&g_deg[src[e]], 1);
    } else {
        int g = (b - 1563) * 256 + threadIdx.x;  // 0..8191
        g_Wc[g] = w_in2[g];
        int i = g >> 6, k = g & 63;
        float s = 0.f;
#pragma unroll 4
        for (int j = 0; j < 128; j++) s += g_Wab[i * 128 + j] * w_in2[j * 64 + k];
        g_Wc[8192 + g] = s;
        if (g < 128) {
            float sb = 0.f;
            for (int j = 0; j < 128; j++) sb += g_Wab[g * 128 + j] * b_in2[j];
            g_bP[g] = sb;
        }
    }
}

// ---------------- scan body ----------------
__device__ void scan_body() {
    __shared__ int wsum[8];
    __shared__ int carry;
    int t = threadIdx.x, l = t & 31, w = t >> 5;
    if (t == 0) { carry = 0; g_rowptr[0] = 0; }
    __syncthreads();
    for (int base = 0; base < NN; base += 256) {
        int v = (base + t < NN) ? g_deg[base + t] : 0;
        int x = v;
#pragma unroll
        for (int o = 1; o < 32; o <<= 1) {
            int y = __shfl_up_sync(0xFFFFFFFFu, x, o);
            if (l >= o) x += y;
        }
        if (l == 31) wsum[w] = x;
        __syncthreads();
        if (w == 0 && l < 8) {
            int y = wsum[l];
#pragma unroll
            for (int o = 1; o < 8; o <<= 1) {
                int z = __shfl_up_sync(0xFFu, y, o);
                if (l >= o) y += z;
            }
            wsum[l] = y;
        }
        __syncthreads();
        int off = carry + (w > 0 ? wsum[w - 1] : 0);
        if (base + t < NN) g_rowptr[base + t + 1] = off + x;
        __syncthreads();
        if (t == 0) carry += wsum[7];
        __syncthreads();
    }
}

// ---------------- K2: fused h+P gemm || scan ----------------
__global__ void __launch_bounds__(256) k2_k(const float* __restrict__ b_in2) {
    int b = blockIdx.x;
    if (b < 626) {
        int bm = (b >> 1) * 64;
        int bn = (b & 1) * 128;
        if (bn == 0) {
            gemm_body<128, false, false>(g_h1, g_Wc, b_in2, g_h, NN, 256, 64, bm, 0, 128);
        } else {
            gemm_body<128, false, true>(g_h1, g_Wc, g_bP - 128, (void*)(g_Ph - 128), NN,
                                        256, 64, bm, 128, 128);
        }
    } else {
        scan_body();
    }
}

// ---------------- K3a: gemm_l0 (313) || scatter (1250) ----------------
__global__ void __launch_bounds__(256) k3a_k(const int* __restrict__ src,
                                             const int* __restrict__ dst) {
    int b = blockIdx.x;
    if (b < 313) {
        gemm_body<128, false, true>(g_h, g_Weff0, nullptr, g_Hth, NN, 128, 128, b * 64,
                                    0, 128);
    } else {
        int e = (b - 313) * 256 + threadIdx.x;
        if (e < EE) {
            int s = src[e];
            int p = atomicAdd(&g_cursor[s], 1);
            int pos = g_rowptr[s] + p;
            g_adjdst[pos] = make_int2(e, dst[e]);
            g_pos[e] = pos;
        }
    }
}

// ---------------- K3b: edge maps in CSR order (warp per node) ----------------
// A-half of src loaded ONCE per node (registers); diag accumulated in registers, no
// atomics. 8 lanes per edge, 4 edges per iteration (one LDG.128 per iteration covers
// all 4 B-row gathers).
__global__ void __launch_bounds__(256) k3b_k(const float* __restrict__ b_map1,
                                             const float* __restrict__ w_map2,
                                             const float* __restrict__ b_map2) {
    const int tid = threadIdx.x;
    const int lane = tid & 31;
    const int wrp = tid >> 5;
    const int n = blockIdx.x * 8 + wrp;
    if (n >= NN) return;
    const int g = lane >> 3;   // edge-in-quad (0..3)
    const int c = lane & 7;    // channel octet (0..7)
    const int ch = c * 8;

    // per-lane weights/biases (registers)
    float4 w0[4], w1[4];
#pragma unroll
    for (int o = 0; o < 4; o++) {
        w0[o] = *(const float4*)(w_map2 + o * 64 + ch);
        w1[o] = *(const float4*)(w_map2 + o * 64 + ch + 4);
    }
    float4 bb0 = *(const float4*)(b_map1 + ch);
    float4 bb1 = *(const float4*)(b_map1 + ch + 4);
    float bm0 = b_map2[0], bm1 = b_map2[1], bm2 = b_map2[2], bm3 = b_map2[3];

    // A octet for this node, folded with bias (computed once)
    float ab[8];
    {
        float4 ar = *(const float4*)(g_Ph + (size_t)n * 128 + ch);
        const __half2* ah = (const __half2*)&ar;
        float2 a01 = __half22float2(ah[0]), a23 = __half22float2(ah[1]);
        float2 a45 = __half22float2(ah[2]), a67 = __half22float2(ah[3]);
        ab[0] = a01.x + bb0.x; ab[1] = a01.y + bb0.y;
        ab[2] = a23.x + bb0.z; ab[3] = a23.y + bb0.w;
        ab[4] = a45.x + bb1.x; ab[5] = a45.y + bb1.y;
        ab[6] = a67.x + bb1.z; ab[7] = a67.y + bb1.w;
    }

    float f00 = 0.f, f01 = 0.f, f11 = 0.f;
    const int beg = g_rowptr[n], end = g_rowptr[n + 1];

    for (int i0 = beg; i0 < end; i0 += 4) {
        int slot = i0 + g;
        bool valid = slot < end;
        int2 ad = valid ? g_adjdst[slot] : make_int2(0, 0);
        float4 br = valid
                        ? *(const float4*)(g_Ph + (size_t)ad.y * 128 + 64 + ch)
                        : make_float4(0.f, 0.f, 0.f, 0.f);
        const __half2* bh = (const __half2*)&br;
        float2 v01 = __half22float2(bh[0]), v23 = __half22float2(bh[1]);
        float2 v45 = __half22float2(bh[2]), v67 = __half22float2(bh[3]);

        float h[8];
        h[0] = fmaxf(ab[0] + v01.x, 0.f);
        h[1] = fmaxf(ab[1] + v01.y, 0.f);
        h[2] = fmaxf(ab[2] + v23.x, 0.f);
        h[3] = fmaxf(ab[3] + v23.y, 0.f);
        h[4] = fmaxf(ab[4] + v45.x, 0.f);
        h[5] = fmaxf(ab[5] + v45.y, 0.f);
        h[6] = fmaxf(ab[6] + v67.x, 0.f);
        h[7] = fmaxf(ab[7] + v67.y, 0.f);

        float p[4];
#pragma unroll
        for (int o = 0; o < 4; o++) {
            p[o] = h[0] * w0[o].x + h[1] * w0[o].y + h[2] * w0[o].z + h[3] * w0[o].w +
                   h[4] * w1[o].x + h[5] * w1[o].y + h[6] * w1[o].z + h[7] * w1[o].w;
        }
#pragma unroll
        for (int o = 0; o < 4; o++) {
            p[o] += __shfl_xor_sync(0xFFFFFFFFu, p[o], 1);
            p[o] += __shfl_xor_sync(0xFFFFFFFFu, p[o], 2);
            p[o] += __shfl_xor_sync(0xFFFFFFFFu, p[o], 4);
        }
        if (valid && c == 0) {
            float m0 = p[0] + bm0;
            float m1 = p[1] + bm1;
            float m2 = p[2] + bm2;
            float m3 = p[3] + bm3;
            ((float4*)g_maps)[ad.x] = make_float4(m0, m1, m2, m3);
            f00 += m0 * m0 + m2 * m2;
            f01 += m0 * m1 + m2 * m3;
            f11 += m1 * m1 + m3 * m3;
        }
    }
    // combine the 4 groups' diag partials (live on lanes 0,8,16,24)
    f00 += __shfl_xor_sync(0xFFFFFFFFu, f00, 8);
    f00 += __shfl_xor_sync(0xFFFFFFFFu, f00, 16);
    f01 += __shfl_xor_sync(0xFFFFFFFFu, f01, 8);
    f01 += __shfl_xor_sync(0xFFFFFFFFu, f01, 16);
    f11 += __shfl_xor_sync(0xFFFFFFFFu, f11, 8);
    f11 += __shfl_xor_sync(0xFFFFFFFFu, f11, 16);
    if (lane == 0) g_diag4[n] = make_float4(f00, f01, f11, 0.f);
}

// ---------------- K4: edge_offn mirrored (625) || diagn (79) ----------------
__global__ void __launch_bounds__(256) k4_k(const int* __restrict__ src,
                                            const int* __restrict__ dst) {
    int b = blockIdx.x;
    if (b < 625) {
        int u = b * 256 + threadIdx.x;
        if (u >= EH) return;
        const float4* maps4 = (const float4*)g_maps;
        float4 me = maps4[u];
        float4 mr = maps4[u + EH];
        float o00 = -(me.x * mr.x + me.z * mr.z);
        float o01 = -(me.x * mr.y + me.z * mr.w);
        float o10 = -(me.y * mr.x + me.w * mr.z);
        float o11 = -(me.y * mr.y + me.w * mr.w);
        int s = src[u], d = dst[u];
        float4 qs = g_diag4[s];
        float4 qd = g_diag4[d];
        float4 Ds = dinv_closed(qs.x, qs.y, qs.z);
        float4 Dd = dinv_closed(qd.x, qd.y, qd.z);
        float t00 = Ds.x * o00 + Ds.y * o10, t01 = Ds.x * o01 + Ds.y * o11;
        float t10 = Ds.z * o00 + Ds.w * o10, t11 = Ds.z * o01 + Ds.w * o11;
        float n00 = t00 * Dd.x + t01 * Dd.z, n01 = t00 * Dd.y + t01 * Dd.w;
        float n10 = t10 * Dd.x + t11 * Dd.z, n11 = t10 * Dd.y + t11 * Dd.w;
        ((float4*)g_offn)[g_pos[u]] = make_float4(n00, n01, n10, n11);
        ((float4*)g_offn)[g_pos[u + EH]] = make_float4(n00, n10, n01, n11);
    } else {
        int n = (b - 625) * 256 + threadIdx.x;
        if (n >= NN) return;
        float4 q = g_diag4[n];
        float f00 = q.x, f01 = q.y, f11 = q.z;
        float4 D = dinv_closed(f00, f01, f11);
        float g00 = f00 * D.x + f01 * D.y, g01 = f00 * D.y + f01 * D.w;
        float g10 = f01 * D.x + f11 * D.y, g11 = f01 * D.y + f11 * D.w;
        float dn00 = D.x * g00 + D.y * g10, dn01 = D.x * g01 + D.y * g11;
        float dn10 = D.y * g00 + D.w * g10, dn11 = D.y * g01 + D.w * g11;
        ((float4*)g_diagn)[n] = make_float4(dn00, dn01, dn10, dn11);
    }
}

// ---------------- aggregation: fp16 Ht gathers, unroll 4 ----------------
__global__ void __launch_bounds__(256) aggregate_k() {
    int w = threadIdx.x >> 5, l = threadIdx.x & 31;
    int n = blockIdx.x * 8 + w;
    if (n >= NN) return;
    const __half2* H2 = (const __half2*)g_Hth;
    float2 hn0 = __half22float2(H2[(size_t)n * 64 + l]);
    float2 hn1 = __half22float2(H2[(size_t)n * 64 + 32 + l]);
    float4 dn = ((const float4*)g_diagn)[n];
    float a0x = dn.x * hn0.x + dn.y * hn1.x;
    float a0y = dn.x * hn0.y + dn.y * hn1.y;
    float a1x = dn.z * hn0.x + dn.w * hn1.x;
    float a1y = dn.z * hn0.y + dn.w * hn1.y;
    int beg = g_rowptr[n], end = g_rowptr[n + 1];
    const float4* offn4 = (const float4*)g_offn;
    int i = beg;
    for (; i + 4 <= end; i += 4) {
        int d0 = g_adjdst[i].y, d1 = g_adjdst[i + 1].y;
        int d2 = g_adjdst[i + 2].y, d3 = g_adjdst[i + 3].y;
        __half2 r00 = H2[(size_t)d0 * 64 + l], r01 = H2[(size_t)d0 * 64 + 32 + l];
        __half2 r10 = H2[(size_t)d1 * 64 + l], r11 = H2[(size_t)d1 * 64 + 32 + l];
        __half2 r20 = H2[(size_t)d2 * 64 + l], r21 = H2[(size_t)d2 * 64 + 32 + l];
        __half2 r30 = H2[(size_t)d3 * 64 + l], r31 = H2[(size_t)d3 * 64 + 32 + l];
        float4 o0 = offn4[i], o1 = offn4[i + 1], o2 = offn4[i + 2], o3 = offn4[i + 3];
        float2 x0, x1;
        x0 = __half22float2(r00); x1 = __half22float2(r01);
        a0x += o0.x * x0.x + o0.y * x1.x;
        a0y += o0.x * x0.y + o0.y * x1.y;
        a1x += o0.z * x0.x + o0.w * x1.x;
        a1y += o0.z * x0.y + o0.w * x1.y;
        x0 = __half22float2(r10); x1 = __half22float2(r11);
        a0x += o1.x * x0.x + o1.y * x1.x;
        a0y += o1.x * x0.y + o1.y * x1.y;
        a1x += o1.z * x0.x + o1.w * x1.x;
        a1y += o1.z * x0.y + o1.w * x1.y;
        x0 = __half22float2(r20); x1 = __half22float2(r21);
        a0x += o2.x * x0.x + o2.y * x1.x;
        a0y += o2.x * x0.y + o2.y * x1.y;
        a1x += o2.z * x0.x + o2.w * x1.x;
        a1y += o2.z * x0.y + o2.w * x1.y;
        x0 = __half22float2(r30); x1 = __half22float2(r31);
        a0x += o3.x * x0.x + o3.y * x1.x;
        a0y += o3.x * x0.y + o3.y * x1.y;
        a1x += o3.z * x0.x + o3.w * x1.x;
        a1y += o3.z * x0.y + o3.w * x1.y;
    }
    for (; i < end; i++) {
        float4 o = offn4[i];
        int dd = g_adjdst[i].y;
        float2 x0 = __half22float2(H2[(size_t)dd * 64 + l]);
        float2 x1 = __half22float2(H2[(size_t)dd * 64 + 32 + l]);
        a0x += o.x * x0.x + o.y * x1.x;
        a0y += o.x * x0.y + o.y * x1.y;
        a1x += o.z * x0.x + o.w * x1.x;
        a1y += o.z * x0.y + o.w * x1.y;
    }
    float2* p0 = (float2*)(g_h + (size_t)n * 128 + 2 * l);
    float2 c0 = *p0;
    c0.x -= eluf(a0x);
    c0.y -= eluf(a0y);
    *p0 = c0;
    float2* p1 = (float2*)(g_h + (size_t)n * 128 + 64 + 2 * l);
    float2 c1 = *p1;
    c1.x -= eluf(a1x);
    c1.y -= eluf(a1y);
    *p1 = c1;
}

// ---------------- plain gemm wrappers ----------------
__global__ void __launch_bounds__(256) gemm_l1_k() {
    gemm_body<128, false, true>(g_h, g_Weff1, nullptr, g_Hth, NN, 128, 128,
                                blockIdx.x * 64, 0, 128);
}
// fused output MLP: block computes its h1 rows, then its out rows (row-local dependency)
__global__ void __launch_bounds__(256) gemm_out_k(const float* __restrict__ w_out1,
                                                  const float* __restrict__ b_out1,
                                                  const float* __restrict__ w_out2,
                                                  const float* __restrict__ b_out2,
                                                  float* __restrict__ out) {
    gemm_body<64, true, false>(g_h, w_out1, b_out1, g_h1, NN, 64, 128, blockIdx.x * 64,
                               0, 64);
    __syncthreads();
    gemm_body<64, false, false>(g_h1, w_out2, b_out2, out, NN, 40, 64, blockIdx.x * 64,
                                0, 40);
}

// ---------------- host ----------------
extern "C" void kernel_launch(void* const* d_in, const int* in_sizes, int n_in,
                              void* d_out, int out_size) {
    (void)in_sizes; (void)n_in; (void)out_size;
    const float* x = (const float*)d_in[0];
    const int* ei = (const int*)d_in[1];
    const int* src = ei;
    const int* dst = ei + EE;
    const float* w_in1 = (const float*)d_in[2];
    const float* b_in1 = (const float*)d_in[3];
    const float* w_in2 = (const float*)d_in[4];
    const float* b_in2 = (const float*)d_in[5];
    const float* w_map1 = (const float*)d_in[6];
    const float* b_map1 = (const float*)d_in[7];
    const float* w_map2 = (const float*)d_in[8];
    const float* b_map2 = (const float*)d_in[9];
    const float* w_out1 = (const float*)d_in[10];
    const float* b_out1 = (const float*)d_in[11];
    const float* w_out2 = (const float*)d_in[12];
    const float* b_out2 = (const float*)d_in[13];
    const float* W1_0 = (const float*)d_in[14];
    const float* W2_0 = (const float*)d_in[15];
    const float* W1_1 = (const float*)d_in[16];
    const float* W2_1 = (const float*)d_in[17];
    float* out = (float*)d_out;

    prep_k<<<79, 256>>>(w_map1, W1_0, W2_0, W1_1, W2_1);
    k1_k<<<313 + 1250 + 32, 256>>>(x, w_in1, b_in1, src, w_in2, b_in2);
    k2_k<<<626 + 1, 256>>>(b_in2);
    k3a_k<<<313 + 1250, 256>>>(src, dst);
    k3b_k<<<2500, 256>>>(b_map1, w_map2, b_map2);
    k4_k<<<625 + 79, 256>>>(src, dst);
    aggregate_k<<<2500, 256>>>();
    gemm_l1_k<<<313, 256>>>();
    aggregate_k<<<2500, 256>>>();
    gemm_out_k<<<313, 256>>>(w_out1, b_out1, w_out2, b_out2, out);
}

// round 16
// speedup vs baseline: 1.0634x; 1.0634x over previous
#include <cuda_runtime.h>
#include <cuda_bf16.h>
#include <cuda_fp16.h>
#include <math.h>
#include <stdint.h>

#define NN 20000
#define EE 320000
#define EH 160000
#define EPSV 1e-6f

// ---------------- scratch (static device globals; no allocs) ----------------
// NOTE: g_deg/g_cursor are zero-initialized at module load and re-zeroed by the
// tail blocks of gemm_out_k at the END of each run, so every run starts clean.
__device__ float g_h1[NN * 64];
__device__ float g_h[NN * 128];
__device__ __half g_Ph[NN * 128];      // [A|B] per node, fp16
__device__ float g_Wc[256 * 64];       // [w_in2 ; Wab@w_in2]
__device__ float g_bP[128];            // Wab @ b_in2
__device__ float g_Weff0[128 * 128];
__device__ float g_Weff1[128 * 128];
__device__ float g_maps[EE * 4];
__device__ float4 g_diag4[NN];         // atomically accumulated FtF per node
__device__ float g_diagn[NN * 4];
__device__ float g_offn[EE * 4];       // CSR order
__device__ __half g_Hth[NN * 128];     // Ht fp16
__device__ int g_deg[NN];
__device__ int g_cursor[NN];
__device__ int g_rowptr[NN + 1];
__device__ int g_dstc[EE];             // CSR slot -> dst node
__device__ int g_pos[EE];              // edge id -> CSR slot

__device__ __forceinline__ float eluf(float v) {
    return v > 0.f ? v : (expf(v) - 1.f);
}

__device__ __forceinline__ float4 dinv_closed(float f00, float f01, float f11) {
    float t = 0.5f * (f00 + f11);
    float dd = 0.5f * (f00 - f11);
    float rad = sqrtf(dd * dd + f01 * f01);
    float s1 = rsqrtf(fmaxf(t - rad, EPSV));
    float s2 = rsqrtf(fmaxf(t + rad, EPSV));
    float c0 = 0.5f * (s1 + s2);
    float c1 = (rad > 1e-20f) ? (s2 - s1) / (2.f * rad) : 0.f;
    return make_float4(c0 + c1 * dd, c1 * f01, c1 * f01, c0 - c1 * dd);
}

__device__ __forceinline__ uint32_t packbf(__nv_bfloat16 a, __nv_bfloat16 b) {
    __nv_bfloat162 t = __halves2bfloat162(a, b);
    return *reinterpret_cast<uint32_t*>(&t);
}

// Wab(i,j): packed edge-MLP first-layer weight view of w_map1 (row-major [64,256])
__device__ __forceinline__ float wab_at(const float* __restrict__ w_map1, int i, int j) {
    return (i < 64) ? w_map1[i * 256 + j] : w_map1[(i - 64) * 256 + 128 + j];
}

#define MMA16816(c, a, b0_, b1_)                                             \
    asm volatile(                                                            \
        "mma.sync.aligned.m16n8k16.row.col.f32.bf16.bf16.f32 "               \
        "{%0,%1,%2,%3}, {%4,%5,%6,%7}, {%8,%9}, {%0,%1,%2,%3};"              \
        : "+f"((c)[0]), "+f"((c)[1]), "+f"((c)[2]), "+f"((c)[3])             \
        : "r"((a)[0]), "r"((a)[1]), "r"((a)[2]), "r"((a)[3]),                \
          "r"(b0_), "r"(b1_))

// ---------------- tensor-core GEMM body; HOUT -> __half output ----------------
template <int BN, bool RELU, bool HOUT>
__device__ __forceinline__ void gemm_body(const float* __restrict__ A,
                                          const float* __restrict__ W,
                                          const float* __restrict__ bias,
                                          void* __restrict__ Cout,
                                          int M, int N, int K, int bm, int bn, int ldc) {
    constexpr int BM = 64;
    constexpr int WN = BN / 4;
    constexpr int NSUB = WN / 8;
    constexpr int SW = 12;

    __shared__ uint32_t sAh[BM * SW], sAl[BM * SW];
    __shared__ uint32_t sWh[BN * SW], sWl[BN * SW];

    const int tid = threadIdx.x;
    const int lane = tid & 31;
    const int wid = tid >> 5;
    const int warp_m = wid & 1;
    const int warp_n = wid >> 1;
    const int qr = lane >> 2;
    const int qc = lane & 3;

    const int lm = tid >> 2;
    const int lk = (tid & 3) * 4;
    const int wof = lk >> 1;

    float acc[2][NSUB][4];
#pragma unroll
    for (int i = 0; i < 2; i++)
#pragma unroll
        for (int j = 0; j < NSUB; j++)
#pragma unroll
            for (int q = 0; q < 4; q++) acc[i][j][q] = 0.f;

    float4 a_reg;
    float4 w_reg[BN / 64];

    auto loadA = [&](int k0) {
        int m = bm + lm;
        a_reg = (m < M) ? *(const float4*)(A + (size_t)m * K + k0 + lk)
                        : make_float4(0.f, 0.f, 0.f, 0.f);
    };
    auto loadW = [&](int k0) {
#pragma unroll
        for (int i = 0; i < BN / 64; i++) {
            int n = bn + lm + i * 64;
            w_reg[i] = (n < N) ? *(const float4*)(W + (size_t)n * K + k0 + lk)
                               : make_float4(0.f, 0.f, 0.f, 0.f);
        }
    };

    auto storeSplit = [&](uint32_t* hi, uint32_t* lo, int row, float4 v) {
        __nv_bfloat16 h0 = __float2bfloat16(v.x), h1 = __float2bfloat16(v.y);
        __nv_bfloat16 h2 = __float2bfloat16(v.z), h3 = __float2bfloat16(v.w);
        __nv_bfloat16 l0 = __float2bfloat16(v.x - __bfloat162float(h0));
        __nv_bfloat16 l1 = __float2bfloat16(v.y - __bfloat162float(h1));
        __nv_bfloat16 l2 = __float2bfloat16(v.z - __bfloat162float(h2));
        __nv_bfloat16 l3 = __float2bfloat16(v.w - __bfloat162float(h3));
        int w0 = row * SW + wof;
        hi[w0 + 0] = packbf(h0, h1);
        hi[w0 + 1] = packbf(h2, h3);
        lo[w0 + 0] = packbf(l0, l1);
        lo[w0 + 1] = packbf(l2, l3);
    };

    loadA(0);
    loadW(0);

    for (int k0 = 0; k0 < K; k0 += 16) {
        storeSplit(sAh, sAl, lm, a_reg);
#pragma unroll
        for (int i = 0; i < BN / 64; i++) storeSplit(sWh, sWl, lm + i * 64, w_reg[i]);
        __syncthreads();

        if (k0 + 16 < K) {
            loadA(k0 + 16);
            loadW(k0 + 16);
        }

        uint32_t ah[2][4], al[2][4];
#pragma unroll
        for (int ms = 0; ms < 2; ms++) {
            int r = warp_m * 32 + ms * 16 + qr;
            int b0 = r * SW + qc;
            ah[ms][0] = sAh[b0];
            ah[ms][1] = sAh[b0 + 8 * SW];
            ah[ms][2] = sAh[b0 + 4];
            ah[ms][3] = sAh[b0 + 8 * SW + 4];
            al[ms][0] = sAl[b0];
            al[ms][1] = sAl[b0 + 8 * SW];
            al[ms][2] = sAl[b0 + 4];
            al[ms][3] = sAl[b0 + 8 * SW + 4];
        }

#pragma unroll
        for (int ns = 0; ns < NSUB; ns++) {
            int n = warp_n * WN + ns * 8 + qr;
            int b = n * SW + qc;
            uint32_t bh0 = sWh[b], bh1 = sWh[b + 4];
            uint32_t bl0 = sWl[b], bl1 = sWl[b + 4];
#pragma unroll
            for (int ms = 0; ms < 2; ms++) {
                MMA16816(acc[ms][ns], ah[ms], bh0, bh1);
                MMA16816(acc[ms][ns], ah[ms], bl0, bl1);
                MMA16816(acc[ms][ns], al[ms], bh0, bh1);
            }
        }
        __syncthreads();
    }

#pragma unroll
    for (int ms = 0; ms < 2; ms++) {
#pragma unroll
        for (int ns = 0; ns < NSUB; ns++) {
            int m0 = bm + warp_m * 32 + ms * 16 + qr;
            int n0 = bn + warp_n * WN + ns * 8 + 2 * qc;
            const float* c = acc[ms][ns];
#pragma unroll
            for (int half = 0; half < 2; half++) {
                int m = m0 + half * 8;
                if (m >= M) continue;
                float v0 = c[half * 2 + 0];
                float v1 = c[half * 2 + 1];
                if (n0 + 1 < N) {
                    v0 += bias ? bias[n0] : 0.f;
                    v1 += bias ? bias[n0 + 1] : 0.f;
                    if (RELU) { v0 = fmaxf(v0, 0.f); v1 = fmaxf(v1, 0.f); }
                    if (HOUT) {
                        *(__half2*)((__half*)Cout + (size_t)m * ldc + n0) =
                            __floats2half2_rn(v0, v1);
                    } else {
                        *(float2*)((float*)Cout + (size_t)m * ldc + n0) =
                            make_float2(v0, v1);
                    }
                } else if (n0 < N) {
                    v0 += bias ? bias[n0] : 0.f;
                    if (RELU) v0 = fmaxf(v0, 0.f);
                    if (HOUT) {
                        ((__half*)Cout)[(size_t)m * ldc + n0] = __float2half_rn(v0);
                    } else {
                        ((float*)Cout)[(size_t)m * ldc + n0] = v0;
                    }
                }
            }
        }
    }
}

// ---------------- K1: input-MLP gemm || hist || Wc combine || Weff build ----------------
__global__ void __launch_bounds__(256) k1_k(const float* __restrict__ x,
                                            const float* __restrict__ w_in1,
                                            const float* __restrict__ b_in1,
                                            const int* __restrict__ src,
                                            const float* __restrict__ w_in2,
                                            const float* __restrict__ b_in2,
                                            const float* __restrict__ w_map1,
                                            const float* __restrict__ W1_0,
                                            const float* __restrict__ W2_0,
                                            const float* __restrict__ W1_1,
                                            const float* __restrict__ W2_1) {
    int b = blockIdx.x;
    if (b < 313) {
        gemm_body<64, true, false>(x, w_in1, b_in1, g_h1, NN, 64, 512, b * 64, 0, 64);
    } else if (b < 1563) {
        int e = (b - 313) * 256 + threadIdx.x;
        if (e < EE) atomicAdd(&g_deg[src[e]], 1);
    } else if (b < 1595) {
        int g = (b - 1563) * 256 + threadIdx.x;  // 0..8191
        g_Wc[g] = w_in2[g];
        int i = g >> 6, k = g & 63;
        float s = 0.f;
#pragma unroll 4
        for (int j = 0; j < 128; j++) s += wab_at(w_map1, i, j) * w_in2[j * 64 + k];
        g_Wc[8192 + g] = s;
        if (g < 128) {
            float sb = 0.f;
            for (int j = 0; j < 128; j++) sb += wab_at(w_map1, g, j) * b_in2[j];
            g_bP[g] = sb;
        }
    } else {
        int i = (b - 1595) * 256 + threadIdx.x;  // 0..16383
        int r = i >> 7, c = i & 127;
        int ii = r >> 6, g = r & 63;
        int jj = c >> 6, f = c & 63;
        g_Weff0[i] = W1_0[jj * 2 + ii] * W2_0[g * 64 + f];
        g_Weff1[i] = W1_1[jj * 2 + ii] * W2_1[g * 64 + f];
    }
}

// ---------------- scan body ----------------
__device__ void scan_body() {
    __shared__ int wsum[8];
    __shared__ int carry;
    int t = threadIdx.x, l = t & 31, w = t >> 5;
    if (t == 0) { carry = 0; g_rowptr[0] = 0; }
    __syncthreads();
    for (int base = 0; base < NN; base += 256) {
        int v = (base + t < NN) ? g_deg[base + t] : 0;
        int x = v;
#pragma unroll
        for (int o = 1; o < 32; o <<= 1) {
            int y = __shfl_up_sync(0xFFFFFFFFu, x, o);
            if (l >= o) x += y;
        }
        if (l == 31) wsum[w] = x;
        __syncthreads();
        if (w == 0 && l < 8) {
            int y = wsum[l];
#pragma unroll
            for (int o = 1; o < 8; o <<= 1) {
                int z = __shfl_up_sync(0xFFu, y, o);
                if (l >= o) y += z;
            }
            wsum[l] = y;
        }
        __syncthreads();
        int off = carry + (w > 0 ? wsum[w - 1] : 0);
        if (base + t < NN) g_rowptr[base + t + 1] = off + x;
        __syncthreads();
        if (t == 0) carry += wsum[7];
        __syncthreads();
    }
}

// ---------------- K2: fused h+P gemm || scan ----------------
__global__ void __launch_bounds__(256) k2_k(const float* __restrict__ b_in2) {
    int b = blockIdx.x;
    if (b < 626) {
        int bm = (b >> 1) * 64;
        int bn = (b & 1) * 128;
        if (bn == 0) {
            gemm_body<128, false, false>(g_h1, g_Wc, b_in2, g_h, NN, 256, 64, bm, 0, 128);
        } else {
            gemm_body<128, false, true>(g_h1, g_Wc, g_bP - 128, (void*)(g_Ph - 128), NN,
                                        256, 64, bm, 128, 128);
        }
    } else {
        scan_body();
    }
}

// ---------------- K3: gemm_l0 (313) || edge maps (2500) || scatter (1250) ---------------
__global__ void __launch_bounds__(256) k3_k(const int* __restrict__ src,
                                            const int* __restrict__ dst,
                                            const float* __restrict__ b_map1,
                                            const float* __restrict__ w_map2,
                                            const float* __restrict__ b_map2) {
    int b = blockIdx.x;
    if (b < 313) {
        gemm_body<128, false, true>(g_h, g_Weff0, nullptr, g_Hth, NN, 128, 128, b * 64,
                                    0, 128);
    } else if (b < 2813) {
        int eb = b - 313;
        __shared__ float sw[256 + 4];   // w_map2 (256) + b_map2 (4)
        const int tid = threadIdx.x;
        if (tid < 256) sw[tid] = w_map2[tid];
        if (tid < 4) sw[256 + tid] = b_map2[tid];
        __syncthreads();

        const int lane = tid & 31;
        const int wrp = tid >> 5;
        const int g = lane >> 3;   // edge within warp group (0..3)
        const int c = lane & 7;    // channel octet (0..7)
        const int ch = c * 8;
        const int ebase = eb * 128 + wrp * 4 + g;

        float4 bb0 = *(const float4*)(b_map1 + ch);
        float4 bb1 = *(const float4*)(b_map1 + ch + 4);

        int sx[4], dx[4];
#pragma unroll
        for (int it = 0; it < 4; it++) {
            sx[it] = src[ebase + it * 32];
            dx[it] = dst[ebase + it * 32];
        }
        float4 ar[4], br[4];
#pragma unroll
        for (int it = 0; it < 4; it++) {
            ar[it] = *(const float4*)(g_Ph + (size_t)sx[it] * 128 + ch);
            br[it] = *(const float4*)(g_Ph + (size_t)dx[it] * 128 + 64 + ch);
        }

#pragma unroll
        for (int it = 0; it < 4; it++) {
            int e = ebase + it * 32;
            const __half2* ah = (const __half2*)&ar[it];
            const __half2* bh = (const __half2*)&br[it];
            float2 a01 = __half22float2(ah[0]), a23 = __half22float2(ah[1]);
            float2 a45 = __half22float2(ah[2]), a67 = __half22float2(ah[3]);
            float2 v01 = __half22float2(bh[0]), v23 = __half22float2(bh[1]);
            float2 v45 = __half22float2(bh[2]), v67 = __half22float2(bh[3]);

            float h[8];
            h[0] = fmaxf(a01.x + v01.x + bb0.x, 0.f);
            h[1] = fmaxf(a01.y + v01.y + bb0.y, 0.f);
            h[2] = fmaxf(a23.x + v23.x + bb0.z, 0.f);
            h[3] = fmaxf(a23.y + v23.y + bb0.w, 0.f);
            h[4] = fmaxf(a45.x + v45.x + bb1.x, 0.f);
            h[5] = fmaxf(a45.y + v45.y + bb1.y, 0.f);
            h[6] = fmaxf(a67.x + v67.x + bb1.z, 0.f);
            h[7] = fmaxf(a67.y + v67.y + bb1.w, 0.f);

            float p[4];
#pragma unroll
            for (int o = 0; o < 4; o++) {
                float4 wa = *(const float4*)(&sw[o * 64 + ch]);
                float4 wb = *(const float4*)(&sw[o * 64 + ch + 4]);
                p[o] = h[0] * wa.x + h[1] * wa.y + h[2] * wa.z + h[3] * wa.w +
                       h[4] * wb.x + h[5] * wb.y + h[6] * wb.z + h[7] * wb.w;
            }
#pragma unroll
            for (int o = 0; o < 4; o++) {
                p[o] += __shfl_xor_sync(0xFFFFFFFFu, p[o], 1);
                p[o] += __shfl_xor_sync(0xFFFFFFFFu, p[o], 2);
                p[o] += __shfl_xor_sync(0xFFFFFFFFu, p[o], 4);
            }
            if (c == 0) {
                float m0 = p[0] + sw[256];
                float m1 = p[1] + sw[257];
                float m2 = p[2] + sw[258];
                float m3 = p[3] + sw[259];
                ((float4*)g_maps)[e] = make_float4(m0, m1, m2, m3);
                float* dg = (float*)&g_diag4[sx[it]];
                atomicAdd(dg + 0, m0 * m0 + m2 * m2);
                atomicAdd(dg + 1, m0 * m1 + m2 * m3);
                atomicAdd(dg + 2, m1 * m1 + m3 * m3);
            }
        }
    } else {
        int e = (b - 2813) * 256 + threadIdx.x;
        if (e < EE) {
            int s = src[e];
            int p = atomicAdd(&g_cursor[s], 1);
            int pos = g_rowptr[s] + p;
            g_dstc[pos] = dst[e];
            g_pos[e] = pos;
        }
    }
}

// ---------------- K4: edge_offn mirrored (625) || diagn (79) ----------------
__global__ void __launch_bounds__(256) k4_k(const int* __restrict__ src,
                                            const int* __restrict__ dst) {
    int b = blockIdx.x;
    if (b < 625) {
        int u = b * 256 + threadIdx.x;
        if (u >= EH) return;
        const float4* maps4 = (const float4*)g_maps;
        float4 me = maps4[u];
        float4 mr = maps4[u + EH];
        float o00 = -(me.x * mr.x + me.z * mr.z);
        float o01 = -(me.x * mr.y + me.z * mr.w);
        float o10 = -(me.y * mr.x + me.w * mr.z);
        float o11 = -(me.y * mr.y + me.w * mr.w);
        int s = src[u], d = dst[u];
        float4 qs = g_diag4[s];
        float4 qd = g_diag4[d];
        float4 Ds = dinv_closed(qs.x, qs.y, qs.z);
        float4 Dd = dinv_closed(qd.x, qd.y, qd.z);
        float t00 = Ds.x * o00 + Ds.y * o10, t01 = Ds.x * o01 + Ds.y * o11;
        float t10 = Ds.z * o00 + Ds.w * o10, t11 = Ds.z * o01 + Ds.w * o11;
        float n00 = t00 * Dd.x + t01 * Dd.z, n01 = t00 * Dd.y + t01 * Dd.w;
        float n10 = t10 * Dd.x + t11 * Dd.z, n11 = t10 * Dd.y + t11 * Dd.w;
        ((float4*)g_offn)[g_pos[u]] = make_float4(n00, n01, n10, n11);
        ((float4*)g_offn)[g_pos[u + EH]] = make_float4(n00, n10, n01, n11);
    } else {
        int n = (b - 625) * 256 + threadIdx.x;
        if (n >= NN) return;
        float4 q = g_diag4[n];
        float f00 = q.x, f01 = q.y, f11 = q.z;
        float4 D = dinv_closed(f00, f01, f11);
        float g00 = f00 * D.x + f01 * D.y, g01 = f00 * D.y + f01 * D.w;
        float g10 = f01 * D.x + f11 * D.y, g11 = f01 * D.y + f11 * D.w;
        float dn00 = D.x * g00 + D.y * g10, dn01 = D.x * g01 + D.y * g11;
        float dn10 = D.y * g00 + D.w * g10, dn11 = D.y * g01 + D.w * g11;
        ((float4*)g_diagn)[n] = make_float4(dn00, dn01, dn10, dn11);
    }
}

// ---------------- aggregation: fp16 Ht gathers, unroll 4 ----------------
__global__ void __launch_bounds__(256) aggregate_k() {
    int w = threadIdx.x >> 5, l = threadIdx.x & 31;
    int n = blockIdx.x * 8 + w;
    if (n >= NN) return;
    const __half2* H2 = (const __half2*)g_Hth;
    float2 hn0 = __half22float2(H2[(size_t)n * 64 + l]);
    float2 hn1 = __half22float2(H2[(size_t)n * 64 + 32 + l]);
    float4 dn = ((const float4*)g_diagn)[n];
    float a0x = dn.x * hn0.x + dn.y * hn1.x;
    float a0y = dn.x * hn0.y + dn.y * hn1.y;
    float a1x = dn.z * hn0.x + dn.w * hn1.x;
    float a1y = dn.z * hn0.y + dn.w * hn1.y;
    int beg = g_rowptr[n], end = g_rowptr[n + 1];
    const float4* offn4 = (const float4*)g_offn;
    int i = beg;
    for (; i + 4 <= end; i += 4) {
        int d0 = g_dstc[i], d1 = g_dstc[i + 1], d2 = g_dstc[i + 2], d3 = g_dstc[i + 3];
        __half2 r00 = H2[(size_t)d0 * 64 + l], r01 = H2[(size_t)d0 * 64 + 32 + l];
        __half2 r10 = H2[(size_t)d1 * 64 + l], r11 = H2[(size_t)d1 * 64 + 32 + l];
        __half2 r20 = H2[(size_t)d2 * 64 + l], r21 = H2[(size_t)d2 * 64 + 32 + l];
        __half2 r30 = H2[(size_t)d3 * 64 + l], r31 = H2[(size_t)d3 * 64 + 32 + l];
        float4 o0 = offn4[i], o1 = offn4[i + 1], o2 = offn4[i + 2], o3 = offn4[i + 3];
        float2 x0, x1;
        x0 = __half22float2(r00); x1 = __half22float2(r01);
        a0x += o0.x * x0.x + o0.y * x1.x;
        a0y += o0.x * x0.y + o0.y * x1.y;
        a1x += o0.z * x0.x + o0.w * x1.x;
        a1y += o0.z * x0.y + o0.w * x1.y;
        x0 = __half22float2(r10); x1 = __half22float2(r11);
        a0x += o1.x * x0.x + o1.y * x1.x;
        a0y += o1.x * x0.y + o1.y * x1.y;
        a1x += o1.z * x0.x + o1.w * x1.x;
        a1y += o1.z * x0.y + o1.w * x1.y;
        x0 = __half22float2(r20); x1 = __half22float2(r21);
        a0x += o2.x * x0.x + o2.y * x1.x;
        a0y += o2.x * x0.y + o2.y * x1.y;
        a1x += o2.z * x0.x + o2.w * x1.x;
        a1y += o2.z * x0.y + o2.w * x1.y;
        x0 = __half22float2(r30); x1 = __half22float2(r31);
        a0x += o3.x * x0.x + o3.y * x1.x;
        a0y += o3.x * x0.y + o3.y * x1.y;
        a1x += o3.z * x0.x + o3.w * x1.x;
        a1y += o3.z * x0.y + o3.w * x1.y;
    }
    for (; i < end; i++) {
        float4 o = offn4[i];
        int dd = g_dstc[i];
        float2 x0 = __half22float2(H2[(size_t)dd * 64 + l]);
        float2 x1 = __half22float2(H2[(size_t)dd * 64 + 32 + l]);
        a0x += o.x * x0.x + o.y * x1.x;
        a0y += o.x * x0.y + o.y * x1.y;
        a1x += o.z * x0.x + o.w * x1.x;
        a1y += o.z * x0.y + o.w * x1.y;
    }
    float2* p0 = (float2*)(g_h + (size_t)n * 128 + 2 * l);
    float2 c0 = *p0;
    c0.x -= eluf(a0x);
    c0.y -= eluf(a0y);
    *p0 = c0;
    float2* p1 = (float2*)(g_h + (size_t)n * 128 + 64 + 2 * l);
    float2 c1 = *p1;
    c1.x -= eluf(a1x);
    c1.y -= eluf(a1y);
    *p1 = c1;
}

// ---------------- plain gemm wrappers ----------------
__global__ void __launch_bounds__(256) gemm_l1_k() {
    gemm_body<128, false, true>(g_h, g_Weff1, nullptr, g_Hth, NN, 128, 128,
                                blockIdx.x * 64, 0, 128);
}
// fused output MLP (313) || counter re-zero for next run (79)
__global__ void __launch_bounds__(256) gemm_out_k(const float* __restrict__ w_out1,
                                                  const float* __restrict__ b_out1,
                                                  const float* __restrict__ w_out2,
                                                  const float* __restrict__ b_out2,
                                                  float* __restrict__ out) {
    int b = blockIdx.x;
    if (b < 313) {
        gemm_body<64, true, false>(g_h, w_out1, b_out1, g_h1, NN, 64, 128, b * 64, 0,
                                   64);
        __syncthreads();
        gemm_body<64, false, false>(g_h1, w_out2, b_out2, out, NN, 40, 64, b * 64, 0,
                                    40);
    } else {
        int n = (b - 313) * 256 + threadIdx.x;
        if (n < NN) {
            g_deg[n] = 0;
            g_cursor[n] = 0;
            g_diag4[n] = make_float4(0.f, 0.f, 0.f, 0.f);
        }
    }
}

// ---------------- host ----------------
extern "C" void kernel_launch(void* const* d_in, const int* in_sizes, int n_in,
                              void* d_out, int out_size) {
    (void)in_sizes; (void)n_in; (void)out_size;
    const float* x = (const float*)d_in[0];
    const int* ei = (const int*)d_in[1];
    const int* src = ei;
    const int* dst = ei + EE;
    const float* w_in1 = (const float*)d_in[2];
    const float* b_in1 = (const float*)d_in[3];
    const float* w_in2 = (const float*)d_in[4];
    const float* b_in2 = (const float*)d_in[5];
    const float* w_map1 = (const float*)d_in[6];
    const float* b_map1 = (const float*)d_in[7];
    const float* w_map2 = (const float*)d_in[8];
    const float* b_map2 = (const float*)d_in[9];
    const float* w_out1 = (const float*)d_in[10];
    const float* b_out1 = (const float*)d_in[11];
    const float* w_out2 = (const float*)d_in[12];
    const float* b_out2 = (const float*)d_in[13];
    const float* W1_0 = (const float*)d_in[14];
    const float* W2_0 = (const float*)d_in[15];
    const float* W1_1 = (const float*)d_in[16];
    const float* W2_1 = (const float*)d_in[17];
    float* out = (float*)d_out;

    k1_k<<<313 + 1250 + 32 + 64, 256>>>(x, w_in1, b_in1, src, w_in2, b_in2, w_map1,
                                        W1_0, W2_0, W1_1, W2_1);
    k2_k<<<626 + 1, 256>>>(b_in2);
    k3_k<<<313 + 2500 + 1250, 256>>>(src, dst, b_map1, w_map2, b_map2);
    k4_k<<<625 + 79, 256>>>(src, dst);
    aggregate_k<<<2500, 256>>>();
    gemm_l1_k<<<313, 256>>>();
    aggregate_k<<<2500, 256>>>();
    gemm_out_k<<<313 + 79, 256>>>(w_out1, b_out1, w_out2, b_out2, out);
}

// round 17
// speedup vs baseline: 1.3000x; 1.2225x over previous
#include <cuda_runtime.h>
#include <cuda_bf16.h>
#include <cuda_fp16.h>
#include <math.h>
#include <stdint.h>

#define NN 20000
#define EE 320000
#define EH 160000
#define EPSV 1e-6f
#define SCANB 79

// ---------------- scratch (static device globals; no allocs) ----------------
// NOTE: g_deg/g_cursor/g_diag4/scan state are zero at module load and re-zeroed by the
// tail blocks of gemm_out_k at the END of each run, so every run starts clean.
__device__ float g_h1[NN * 64];
__device__ float g_h[NN * 128];
__device__ __half g_Ph[NN * 128];      // [A|B] per node, fp16
__device__ float g_Wc[256 * 64];       // [w_in2 ; Wab@w_in2]
__device__ float g_bP[128];            // Wab @ b_in2
__device__ float g_Weff0[128 * 128];
__device__ float g_Weff1[128 * 128];
__device__ float g_maps[EE * 4];
__device__ float4 g_diag4[NN];         // atomically accumulated FtF per node
__device__ float g_diagn[NN * 4];
__device__ float g_offn[EE * 4];       // CSR order
__device__ __half g_Hth[NN * 128];     // Ht fp16
__device__ int g_deg[NN];
__device__ int g_cursor[NN];
__device__ int g_rowptr[NN + 1];
__device__ int g_dstc[EE];             // CSR slot -> dst node
__device__ int g_pos[EE];              // edge id -> CSR slot
__device__ int g_scan_agg[SCANB];
__device__ int g_scan_inc[SCANB];
__device__ int g_scan_flag[SCANB];     // 0 none, 1 agg ready, 2 inclusive ready

__device__ __forceinline__ float eluf(float v) {
    return v > 0.f ? v : (expf(v) - 1.f);
}

__device__ __forceinline__ float4 dinv_closed(float f00, float f01, float f11) {
    float t = 0.5f * (f00 + f11);
    float dd = 0.5f * (f00 - f11);
    float rad = sqrtf(dd * dd + f01 * f01);
    float s1 = rsqrtf(fmaxf(t - rad, EPSV));
    float s2 = rsqrtf(fmaxf(t + rad, EPSV));
    float c0 = 0.5f * (s1 + s2);
    float c1 = (rad > 1e-20f) ? (s2 - s1) / (2.f * rad) : 0.f;
    return make_float4(c0 + c1 * dd, c1 * f01, c1 * f01, c0 - c1 * dd);
}

__device__ __forceinline__ uint32_t packbf(__nv_bfloat16 a, __nv_bfloat16 b) {
    __nv_bfloat162 t = __halves2bfloat162(a, b);
    return *reinterpret_cast<uint32_t*>(&t);
}

// Wab(i,j): packed edge-MLP first-layer weight view of w_map1 (row-major [64,256])
__device__ __forceinline__ float wab_at(const float* __restrict__ w_map1, int i, int j) {
    return (i < 64) ? w_map1[i * 256 + j] : w_map1[(i - 64) * 256 + 128 + j];
}

#define MMA16816(c, a, b0_, b1_)                                             \
    asm volatile(                                                            \
        "mma.sync.aligned.m16n8k16.row.col.f32.bf16.bf16.f32 "               \
        "{%0,%1,%2,%3}, {%4,%5,%6,%7}, {%8,%9}, {%0,%1,%2,%3};"              \
        : "+f"((c)[0]), "+f"((c)[1]), "+f"((c)[2]), "+f"((c)[3])             \
        : "r"((a)[0]), "r"((a)[1]), "r"((a)[2]), "r"((a)[3]),                \
          "r"(b0_), "r"(b1_))

// ---------------- tensor-core GEMM body; HOUT -> __half output ----------------
template <int BN, bool RELU, bool HOUT>
__device__ __forceinline__ void gemm_body(const float* __restrict__ A,
                                          const float* __restrict__ W,
                                          const float* __restrict__ bias,
                                          void* __restrict__ Cout,
                                          int M, int N, int K, int bm, int bn, int ldc) {
    constexpr int BM = 64;
    constexpr int WN = BN / 4;
    constexpr int NSUB = WN / 8;
    constexpr int SW = 12;

    __shared__ uint32_t sAh[BM * SW], sAl[BM * SW];
    __shared__ uint32_t sWh[BN * SW], sWl[BN * SW];

    const int tid = threadIdx.x;
    const int lane = tid & 31;
    const int wid = tid >> 5;
    const int warp_m = wid & 1;
    const int warp_n = wid >> 1;
    const int qr = lane >> 2;
    const int qc = lane & 3;

    const int lm = tid >> 2;
    const int lk = (tid & 3) * 4;
    const int wof = lk >> 1;

    float acc[2][NSUB][4];
#pragma unroll
    for (int i = 0; i < 2; i++)
#pragma unroll
        for (int j = 0; j < NSUB; j++)
#pragma unroll
            for (int q = 0; q < 4; q++) acc[i][j][q] = 0.f;

    float4 a_reg;
    float4 w_reg[BN / 64];

    auto loadA = [&](int k0) {
        int m = bm + lm;
        a_reg = (m < M) ? *(const float4*)(A + (size_t)m * K + k0 + lk)
                        : make_float4(0.f, 0.f, 0.f, 0.f);
    };
    auto loadW = [&](int k0) {
#pragma unroll
        for (int i = 0; i < BN / 64; i++) {
            int n = bn + lm + i * 64;
            w_reg[i] = (n < N) ? *(const float4*)(W + (size_t)n * K + k0 + lk)
                               : make_float4(0.f, 0.f, 0.f, 0.f);
        }
    };

    auto storeSplit = [&](uint32_t* hi, uint32_t* lo, int row, float4 v) {
        __nv_bfloat16 h0 = __float2bfloat16(v.x), h1 = __float2bfloat16(v.y);
        __nv_bfloat16 h2 = __float2bfloat16(v.z), h3 = __float2bfloat16(v.w);
        __nv_bfloat16 l0 = __float2bfloat16(v.x - __bfloat162float(h0));
        __nv_bfloat16 l1 = __float2bfloat16(v.y - __bfloat162float(h1));
        __nv_bfloat16 l2 = __float2bfloat16(v.z - __bfloat162float(h2));
        __nv_bfloat16 l3 = __float2bfloat16(v.w - __bfloat162float(h3));
        int w0 = row * SW + wof;
        hi[w0 + 0] = packbf(h0, h1);
        hi[w0 + 1] = packbf(h2, h3);
        lo[w0 + 0] = packbf(l0, l1);
        lo[w0 + 1] = packbf(l2, l3);
    };

    loadA(0);
    loadW(0);

    for (int k0 = 0; k0 < K; k0 += 16) {
        storeSplit(sAh, sAl, lm, a_reg);
#pragma unroll
        for (int i = 0; i < BN / 64; i++) storeSplit(sWh, sWl, lm + i * 64, w_reg[i]);
        __syncthreads();

        if (k0 + 16 < K) {
            loadA(k0 + 16);
            loadW(k0 + 16);
        }

        uint32_t ah[2][4], al[2][4];
#pragma unroll
        for (int ms = 0; ms < 2; ms++) {
            int r = warp_m * 32 + ms * 16 + qr;
            int b0 = r * SW + qc;
            ah[ms][0] = sAh[b0];
            ah[ms][1] = sAh[b0 + 8 * SW];
            ah[ms][2] = sAh[b0 + 4];
            ah[ms][3] = sAh[b0 + 8 * SW + 4];
            al[ms][0] = sAl[b0];
            al[ms][1] = sAl[b0 + 8 * SW];
            al[ms][2] = sAl[b0 + 4];
            al[ms][3] = sAl[b0 + 8 * SW + 4];
        }

#pragma unroll
        for (int ns = 0; ns < NSUB; ns++) {
            int n = warp_n * WN + ns * 8 + qr;
            int b = n * SW + qc;
            uint32_t bh0 = sWh[b], bh1 = sWh[b + 4];
            uint32_t bl0 = sWl[b], bl1 = sWl[b + 4];
#pragma unroll
            for (int ms = 0; ms < 2; ms++) {
                MMA16816(acc[ms][ns], ah[ms], bh0, bh1);
                MMA16816(acc[ms][ns], ah[ms], bl0, bl1);
                MMA16816(acc[ms][ns], al[ms], bh0, bh1);
            }
        }
        __syncthreads();
    }

#pragma unroll
    for (int ms = 0; ms < 2; ms++) {
#pragma unroll
        for (int ns = 0; ns < NSUB; ns++) {
            int m0 = bm + warp_m * 32 + ms * 16 + qr;
            int n0 = bn + warp_n * WN + ns * 8 + 2 * qc;
            const float* c = acc[ms][ns];
#pragma unroll
            for (int half = 0; half < 2; half++) {
                int m = m0 + half * 8;
                if (m >= M) continue;
                float v0 = c[half * 2 + 0];
                float v1 = c[half * 2 + 1];
                if (n0 + 1 < N) {
                    v0 += bias ? bias[n0] : 0.f;
                    v1 += bias ? bias[n0 + 1] : 0.f;
                    if (RELU) { v0 = fmaxf(v0, 0.f); v1 = fmaxf(v1, 0.f); }
                    if (HOUT) {
                        *(__half2*)((__half*)Cout + (size_t)m * ldc + n0) =
                            __floats2half2_rn(v0, v1);
                    } else {
                        *(float2*)((float*)Cout + (size_t)m * ldc + n0) =
                            make_float2(v0, v1);
                    }
                } else if (n0 < N) {
                    v0 += bias ? bias[n0] : 0.f;
                    if (RELU) v0 = fmaxf(v0, 0.f);
                    if (HOUT) {
                        ((__half*)Cout)[(size_t)m * ldc + n0] = __float2half_rn(v0);
                    } else {
                        ((float*)Cout)[(size_t)m * ldc + n0] = v0;
                    }
                }
            }
        }
    }
}

// ---------------- K1: input-MLP gemm || hist || Wc combine || Weff build ----------------
__global__ void __launch_bounds__(256) k1_k(const float* __restrict__ x,
                                            const float* __restrict__ w_in1,
                                            const float* __restrict__ b_in1,
                                            const int* __restrict__ src,
                                            const float* __restrict__ w_in2,
                                            const float* __restrict__ b_in2,
                                            const float* __restrict__ w_map1,
                                            const float* __restrict__ W1_0,
                                            const float* __restrict__ W2_0,
                                            const float* __restrict__ W1_1,
                                            const float* __restrict__ W2_1) {
    int b = blockIdx.x;
    if (b < 313) {
        gemm_body<64, true, false>(x, w_in1, b_in1, g_h1, NN, 64, 512, b * 64, 0, 64);
    } else if (b < 1563) {
        int e = (b - 313) * 256 + threadIdx.x;
        if (e < EE) atomicAdd(&g_deg[src[e]], 1);
    } else if (b < 1595) {
        int g = (b - 1563) * 256 + threadIdx.x;  // 0..8191
        g_Wc[g] = w_in2[g];
        int i = g >> 6, k = g & 63;
        float s = 0.f;
#pragma unroll 4
        for (int j = 0; j < 128; j++) s += wab_at(w_map1, i, j) * w_in2[j * 64 + k];
        g_Wc[8192 + g] = s;
        if (g < 128) {
            float sb = 0.f;
            for (int j = 0; j < 128; j++) sb += wab_at(w_map1, g, j) * b_in2[j];
            g_bP[g] = sb;
        }
    } else {
        int i = (b - 1595) * 256 + threadIdx.x;  // 0..16383
        int r = i >> 7, c = i & 127;
        int ii = r >> 6, g = r & 63;
        int jj = c >> 6, f = c & 63;
        g_Weff0[i] = W1_0[jj * 2 + ii] * W2_0[g * 64 + f];
        g_Weff1[i] = W1_1[jj * 2 + ii] * W2_1[g * 64 + f];
    }
}

// ---------------- decoupled-lookback scan block (256 elems per block) ----------------
__device__ void scan_block(int sb) {
    __shared__ int wsum[8];
    __shared__ int s_prefix;
    int t = threadIdx.x, l = t & 31, w = t >> 5;
    int i = sb * 256 + t;
    int v = (i < NN) ? g_deg[i] : 0;
    int x = v;
#pragma unroll
    for (int o = 1; o < 32; o <<= 1) {
        int y = __shfl_up_sync(0xFFFFFFFFu, x, o);
        if (l >= o) x += y;
    }
    if (l == 31) wsum[w] = x;
    __syncthreads();
    if (t < 8) {
        int y = wsum[t];
#pragma unroll
        for (int o = 1; o < 8; o <<= 1) {
            int z = __shfl_up_sync(0xFFu, y, o);
            if (t >= o) y += z;
        }
        wsum[t] = y;
    }
    __syncthreads();
    int incl = x + (w > 0 ? wsum[w - 1] : 0);
    int total = wsum[7];
    if (t == 0) {
        if (sb == 0) {
            g_scan_inc[0] = total;
            __threadfence();
            atomicExch(&g_scan_flag[0], 2);
            s_prefix = 0;
        } else {
            g_scan_agg[sb] = total;
            __threadfence();
            atomicExch(&g_scan_flag[sb], 1);
            int prefix = 0;
            int j = sb - 1;
            while (true) {
                int f;
                while ((f = atomicAdd(&g_scan_flag[j], 0)) == 0) { }
                if (f == 2) {
                    prefix += atomicAdd(&g_scan_inc[j], 0);
                    break;
                }
                prefix += atomicAdd(&g_scan_agg[j], 0);
                j--;
            }
            g_scan_inc[sb] = prefix + total;
            __threadfence();
            atomicExch(&g_scan_flag[sb], 2);
            s_prefix = prefix;
        }
    }
    __syncthreads();
    if (i < NN) g_rowptr[i + 1] = s_prefix + incl;
    if (sb == 0 && t == 0) g_rowptr[0] = 0;
}

// ---------------- K2: scan (79, first => wave-1 co-resident) || fused h+P gemm (626) ----
__global__ void __launch_bounds__(256) k2_k(const float* __restrict__ b_in2) {
    int b = blockIdx.x;
    if (b < SCANB) {
        scan_block(b);
    } else {
        int gb = b - SCANB;
        int bm = (gb >> 1) * 64;
        int bn = (gb & 1) * 128;
        if (bn == 0) {
            gemm_body<128, false, false>(g_h1, g_Wc, b_in2, g_h, NN, 256, 64, bm, 0, 128);
        } else {
            gemm_body<128, false, true>(g_h1, g_Wc, g_bP - 128, (void*)(g_Ph - 128), NN,
                                        256, 64, bm, 128, 128);
        }
    }
}

// ---------------- K3: gemm_l0 (313) || edge maps (2500) || scatter (1250) ---------------
__global__ void __launch_bounds__(256) k3_k(const int* __restrict__ src,
                                            const int* __restrict__ dst,
                                            const float* __restrict__ b_map1,
                                            const float* __restrict__ w_map2,
                                            const float* __restrict__ b_map2) {
    int b = blockIdx.x;
    if (b < 313) {
        gemm_body<128, false, true>(g_h, g_Weff0, nullptr, g_Hth, NN, 128, 128, b * 64,
                                    0, 128);
    } else if (b < 2813) {
        int eb = b - 313;
        __shared__ float sw[256 + 4];   // w_map2 (256) + b_map2 (4)
        const int tid = threadIdx.x;
        if (tid < 256) sw[tid] = w_map2[tid];
        if (tid < 4) sw[256 + tid] = b_map2[tid];
        __syncthreads();

        const int lane = tid & 31;
        const int wrp = tid >> 5;
        const int g = lane >> 3;   // edge within warp group (0..3)
        const int c = lane & 7;    // channel octet (0..7)
        const int ch = c * 8;
        const int ebase = eb * 128 + wrp * 4 + g;

        float4 bb0 = *(const float4*)(b_map1 + ch);
        float4 bb1 = *(const float4*)(b_map1 + ch + 4);

        int sx[4], dx[4];
#pragma unroll
        for (int it = 0; it < 4; it++) {
            sx[it] = src[ebase + it * 32];
            dx[it] = dst[ebase + it * 32];
        }
        float4 ar[4], br[4];
#pragma unroll
        for (int it = 0; it < 4; it++) {
            ar[it] = *(const float4*)(g_Ph + (size_t)sx[it] * 128 + ch);
            br[it] = *(const float4*)(g_Ph + (size_t)dx[it] * 128 + 64 + ch);
        }

#pragma unroll
        for (int it = 0; it < 4; it++) {
            int e = ebase + it * 32;
            const __half2* ah = (const __half2*)&ar[it];
            const __half2* bh = (const __half2*)&br[it];
            float2 a01 = __half22float2(ah[0]), a23 = __half22float2(ah[1]);
            float2 a45 = __half22float2(ah[2]), a67 = __half22float2(ah[3]);
            float2 v01 = __half22float2(bh[0]), v23 = __half22float2(bh[1]);
            float2 v45 = __half22float2(bh[2]), v67 = __half22float2(bh[3]);

            float h[8];
            h[0] = fmaxf(a01.x + v01.x + bb0.x, 0.f);
            h[1] = fmaxf(a01.y + v01.y + bb0.y, 0.f);
            h[2] = fmaxf(a23.x + v23.x + bb0.z, 0.f);
            h[3] = fmaxf(a23.y + v23.y + bb0.w, 0.f);
            h[4] = fmaxf(a45.x + v45.x + bb1.x, 0.f);
            h[5] = fmaxf(a45.y + v45.y + bb1.y, 0.f);
            h[6] = fmaxf(a67.x + v67.x + bb1.z, 0.f);
            h[7] = fmaxf(a67.y + v67.y + bb1.w, 0.f);

            float p[4];
#pragma unroll
            for (int o = 0; o < 4; o++) {
                float4 wa = *(const float4*)(&sw[o * 64 + ch]);
                float4 wb = *(const float4*)(&sw[o * 64 + ch + 4]);
                p[o] = h[0] * wa.x + h[1] * wa.y + h[2] * wa.z + h[3] * wa.w +
                       h[4] * wb.x + h[5] * wb.y + h[6] * wb.z + h[7] * wb.w;
            }
#pragma unroll
            for (int o = 0; o < 4; o++) {
                p[o] += __shfl_xor_sync(0xFFFFFFFFu, p[o], 1);
                p[o] += __shfl_xor_sync(0xFFFFFFFFu, p[o], 2);
                p[o] += __shfl_xor_sync(0xFFFFFFFFu, p[o], 4);
            }
            if (c == 0) {
                float m0 = p[0] + sw[256];
                float m1 = p[1] + sw[257];
                float m2 = p[2] + sw[258];
                float m3 = p[3] + sw[259];
                ((float4*)g_maps)[e] = make_float4(m0, m1, m2, m3);
                float* dg = (float*)&g_diag4[sx[it]];
                atomicAdd(dg + 0, m0 * m0 + m2 * m2);
                atomicAdd(dg + 1, m0 * m1 + m2 * m3);
                atomicAdd(dg + 2, m1 * m1 + m3 * m3);
            }
        }
    } else {
        int e = (b - 2813) * 256 + threadIdx.x;
        if (e < EE) {
            int s = src[e];
            int p = atomicAdd(&g_cursor[s], 1);
            int pos = g_rowptr[s] + p;
            g_dstc[pos] = dst[e];
            g_pos[e] = pos;
        }
    }
}

// ---------------- K4: edge_offn mirrored (625) || diagn (79) ----------------
__global__ void __launch_bounds__(256) k4_k(const int* __restrict__ src,
                                            const int* __restrict__ dst) {
    int b = blockIdx.x;
    if (b < 625) {
        int u = b * 256 + threadIdx.x;
        if (u >= EH) return;
        const float4* maps4 = (const float4*)g_maps;
        float4 me = maps4[u];
        float4 mr = maps4[u + EH];
        float o00 = -(me.x * mr.x + me.z * mr.z);
        float o01 = -(me.x * mr.y + me.z * mr.w);
        float o10 = -(me.y * mr.x + me.w * mr.z);
        float o11 = -(me.y * mr.y + me.w * mr.w);
        int s = src[u], d = dst[u];
        float4 qs = g_diag4[s];
        float4 qd = g_diag4[d];
        float4 Ds = dinv_closed(qs.x, qs.y, qs.z);
        float4 Dd = dinv_closed(qd.x, qd.y, qd.z);
        float t00 = Ds.x * o00 + Ds.y * o10, t01 = Ds.x * o01 + Ds.y * o11;
        float t10 = Ds.z * o00 + Ds.w * o10, t11 = Ds.z * o01 + Ds.w * o11;
        float n00 = t00 * Dd.x + t01 * Dd.z, n01 = t00 * Dd.y + t01 * Dd.w;
        float n10 = t10 * Dd.x + t11 * Dd.z, n11 = t10 * Dd.y + t11 * Dd.w;
        ((float4*)g_offn)[g_pos[u]] = make_float4(n00, n01, n10, n11);
        ((float4*)g_offn)[g_pos[u + EH]] = make_float4(n00, n10, n01, n11);
    } else {
        int n = (b - 625) * 256 + threadIdx.x;
        if (n >= NN) return;
        float4 q = g_diag4[n];
        float f00 = q.x, f01 = q.y, f11 = q.z;
        float4 D = dinv_closed(f00, f01, f11);
        float g00 = f00 * D.x + f01 * D.y, g01 = f00 * D.y + f01 * D.w;
        float g10 = f01 * D.x + f11 * D.y, g11 = f01 * D.y + f11 * D.w;
        float dn00 = D.x * g00 + D.y * g10, dn01 = D.x * g01 + D.y * g11;
        float dn10 = D.y * g00 + D.w * g10, dn11 = D.y * g01 + D.w * g11;
        ((float4*)g_diagn)[n] = make_float4(dn00, dn01, dn10, dn11);
    }
}

// ---------------- aggregation: fp16 Ht gathers, unroll 4 ----------------
__global__ void __launch_bounds__(256) aggregate_k() {
    int w = threadIdx.x >> 5, l = threadIdx.x & 31;
    int n = blockIdx.x * 8 + w;
    if (n >= NN) return;
    const __half2* H2 = (const __half2*)g_Hth;
    float2 hn0 = __half22float2(H2[(size_t)n * 64 + l]);
    float2 hn1 = __half22float2(H2[(size_t)n * 64 + 32 + l]);
    float4 dn = ((const float4*)g_diagn)[n];
    float a0x = dn.x * hn0.x + dn.y * hn1.x;
    float a0y = dn.x * hn0.y + dn.y * hn1.y;
    float a1x = dn.z * hn0.x + dn.w * hn1.x;
    float a1y = dn.z * hn0.y + dn.w * hn1.y;
    int beg = g_rowptr[n], end = g_rowptr[n + 1];
    const float4* offn4 = (const float4*)g_offn;
    int i = beg;
    for (; i + 4 <= end; i += 4) {
        int d0 = g_dstc[i], d1 = g_dstc[i + 1], d2 = g_dstc[i + 2], d3 = g_dstc[i + 3];
        __half2 r00 = H2[(size_t)d0 * 64 + l], r01 = H2[(size_t)d0 * 64 + 32 + l];
        __half2 r10 = H2[(size_t)d1 * 64 + l], r11 = H2[(size_t)d1 * 64 + 32 + l];
        __half2 r20 = H2[(size_t)d2 * 64 + l], r21 = H2[(size_t)d2 * 64 + 32 + l];
        __half2 r30 = H2[(size_t)d3 * 64 + l], r31 = H2[(size_t)d3 * 64 + 32 + l];
        float4 o0 = offn4[i], o1 = offn4[i + 1], o2 = offn4[i + 2], o3 = offn4[i + 3];
        float2 x0, x1;
        x0 = __half22float2(r00); x1 = __half22float2(r01);
        a0x += o0.x * x0.x + o0.y * x1.x;
        a0y += o0.x * x0.y + o0.y * x1.y;
        a1x += o0.z * x0.x + o0.w * x1.x;
        a1y += o0.z * x0.y + o0.w * x1.y;
        x0 = __half22float2(r10); x1 = __half22float2(r11);
        a0x += o1.x * x0.x + o1.y * x1.x;
        a0y += o1.x * x0.y + o1.y * x1.y;
        a1x += o1.z * x0.x + o1.w * x1.x;
        a1y += o1.z * x0.y + o1.w * x1.y;
        x0 = __half22float2(r20); x1 = __half22float2(r21);
        a0x += o2.x * x0.x + o2.y * x1.x;
        a0y += o2.x * x0.y + o2.y * x1.y;
        a1x += o2.z * x0.x + o2.w * x1.x;
        a1y += o2.z * x0.y + o2.w * x1.y;
        x0 = __half22float2(r30); x1 = __half22float2(r31);
        a0x += o3.x * x0.x + o3.y * x1.x;
        a0y += o3.x * x0.y + o3.y * x1.y;
        a1x += o3.z * x0.x + o3.w * x1.x;
        a1y += o3.z * x0.y + o3.w * x1.y;
    }
    for (; i < end; i++) {
        float4 o = offn4[i];
        int dd = g_dstc[i];
        float2 x0 = __half22float2(H2[(size_t)dd * 64 + l]);
        float2 x1 = __half22float2(H2[(size_t)dd * 64 + 32 + l]);
        a0x += o.x * x0.x + o.y * x1.x;
        a0y += o.x * x0.y + o.y * x1.y;
        a1x += o.z * x0.x + o.w * x1.x;
        a1y += o.z * x0.y + o.w * x1.y;
    }
    float2* p0 = (float2*)(g_h + (size_t)n * 128 + 2 * l);
    float2 c0 = *p0;
    c0.x -= eluf(a0x);
    c0.y -= eluf(a0y);
    *p0 = c0;
    float2* p1 = (float2*)(g_h + (size_t)n * 128 + 64 + 2 * l);
    float2 c1 = *p1;
    c1.x -= eluf(a1x);
    c1.y -= eluf(a1y);
    *p1 = c1;
}

// ---------------- plain gemm wrappers ----------------
__global__ void __launch_bounds__(256) gemm_l1_k() {
    gemm_body<128, false, true>(g_h, g_Weff1, nullptr, g_Hth, NN, 128, 128,
                                blockIdx.x * 64, 0, 128);
}
// fused output MLP (313) || counter/scan-state re-zero for next run (79)
__global__ void __launch_bounds__(256) gemm_out_k(const float* __restrict__ w_out1,
                                                  const float* __restrict__ b_out1,
                                                  const float* __restrict__ w_out2,
                                                  const float* __restrict__ b_out2,
                                                  float* __restrict__ out) {
    int b = blockIdx.x;
    if (b < 313) {
        gemm_body<64, true, false>(g_h, w_out1, b_out1, g_h1, NN, 64, 128, b * 64, 0,
                                   64);
        __syncthreads();
        gemm_body<64, false, false>(g_h1, w_out2, b_out2, out, NN, 40, 64, b * 64, 0,
                                    40);
    } else {
        int n = (b - 313) * 256 + threadIdx.x;
        if (n < NN) {
            g_deg[n] = 0;
            g_cursor[n] = 0;
            g_diag4[n] = make_float4(0.f, 0.f, 0.f, 0.f);
        }
        if (n < SCANB) {
            g_scan_agg[n] = 0;
            g_scan_inc[n] = 0;
            g_scan_flag[n] = 0;
        }
    }
}

// ---------------- host ----------------
extern "C" void kernel_launch(void* const* d_in, const int* in_sizes, int n_in,
                              void* d_out, int out_size) {
    (void)in_sizes; (void)n_in; (void)out_size;
    const float* x = (const float*)d_in[0];
    const int* ei = (const int*)d_in[1];
    const int* src = ei;
    const int* dst = ei + EE;
    const float* w_in1 = (const float*)d_in[2];
    const float* b_in1 = (const float*)d_in[3];
    const float* w_in2 = (const float*)d_in[4];
    const float* b_in2 = (const float*)d_in[5];
    const float* w_map1 = (const float*)d_in[6];
    const float* b_map1 = (const float*)d_in[7];
    const float* w_map2 = (const float*)d_in[8];
    const float* b_map2 = (const float*)d_in[9];
    const float* w_out1 = (const float*)d_in[10];
    const float* b_out1 = (const float*)d_in[11];
    const float* w_out2 = (const float*)d_in[12];
    const float* b_out2 = (const float*)d_in[13];
    const float* W1_0 = (const float*)d_in[14];
    const float* W2_0 = (const float*)d_in[15];
    const float* W1_1 = (const float*)d_in[16];
    const float* W2_1 = (const float*)d_in[17];
    float* out = (float*)d_out;

    k1_k<<<313 + 1250 + 32 + 64, 256>>>(x, w_in1, b_in1, src, w_in2, b_in2, w_map1,
                                        W1_0, W2_0, W1_1, W2_1);
    k2_k<<<SCANB + 626, 256>>>(b_in2);
    k3_k<<<313 + 2500 + 1250, 256>>>(src, dst, b_map1, w_map2, b_map2);
    k4_k<<<625 + 79, 256>>>(src, dst);
    aggregate_k<<<2500, 256>>>();
    gemm_l1_k<<<313, 256>>>();
    aggregate_k<<<2500, 256>>>();
    gemm_out_k<<<313 + 79, 256>>>(w_out1, b_out1, w_out2, b_out2, out);
}